// round 14
// baseline (speedup 1.0000x reference)
#include <cuda_runtime.h>
#include <float.h>
#include <math.h>

// CropRoi: f (4,64,32,32,32) f32; proposals (96,8) f32; out (96,64,7,7,7) f32.
// Box: c0 = max(floor((c-s/2)/4),0), c1 = min(ceil((c+s/2)/4),32); L in [1,14].
// Adaptive windows per axis: size 1..3, always in-range -> plain max.
//
// R2 (thread-per-bin) remains fastest; its issue cost is divergent-loop
// replay: warps execute max-lane trip counts (~165 instr/warp vs ~55 useful).
// Per axis the 7 windows have only TWO sizes {floor(L/7), ceil(L/7)}, so bins
// fall into <=27 (nd,nh,nw) classes. The precompute kernel counting-sorts the
// 343 bins by class; pool thread t works on sorted slot t -> warp-uniform
// exact trip counts (only class-boundary warps diverge). Results are placed
// via a smem transpose so the final STG stays fully coalesced.

#define RBINS 7
#define NBINS 343
#define FDIM 32
#define MAXN 128

__device__ int g_sdesc[MAXN * NBINS];  // start:15 | bin:9 | nd:2 | nh:2 | nw:2
__device__ int g_base[MAXN];

__global__ void precompute_kernel(const float* __restrict__ props)
{
    const int n = blockIdx.x;
    const int t = threadIdx.x;
    const float* p = props + n * 8;

    int c0[3], L[3];
#pragma unroll
    for (int ax = 0; ax < 3; ++ax) {
        const float ce = p[2 + ax], si = p[5 + ax];
        int lo = (int)floorf((ce - si * 0.5f) * 0.25f);
        int hi = (int)ceilf ((ce + si * 0.5f) * 0.25f);
        lo = max(lo, 0); hi = min(hi, FDIM);
        c0[ax] = lo;
        L[ax]  = max(hi - lo, 1);
    }

    if (t == 0) {
        const int b = (int)p[0];
        g_base[n] = ((b * 64) << 15) +
                    ((c0[0] * FDIM + c0[1]) * FDIM + c0[2]);
    }

    __shared__ int hist[27];
    __shared__ int offs[27];
    if (t < 27) hist[t] = 0;
    __syncthreads();

    int key = 0, desc = 0;
    if (t < NBINS) {
        const int k = t % RBINS;
        const int j = (t / RBINS) % RBINS;
        const int i = t / (RBINS * RBINS);

        const int ds = (i * L[0]) / RBINS, de = ((i + 1) * L[0] + RBINS - 1) / RBINS;
        const int hs = (j * L[1]) / RBINS, he = ((j + 1) * L[1] + RBINS - 1) / RBINS;
        const int ws = (k * L[2]) / RBINS, we = ((k + 1) * L[2] + RBINS - 1) / RBINS;

        const int nd = de - ds - 1, nh = he - hs - 1, nw = we - ws - 1; // 0..2
        const int start = (ds * FDIM + hs) * FDIM + ws;                 // 15 bits

        key  = (nd * 3 + nh) * 3 + nw;
        desc = start | (t << 15) | (nd << 24) | (nh << 26) | (nw << 28);
        atomicAdd(&hist[key], 1);
    }
    __syncthreads();

    if (t == 0) {
        int s = 0;
        for (int q = 0; q < 27; ++q) { offs[q] = s; s += hist[q]; }
    }
    __syncthreads();

    if (t < NBINS) {
        const int rank = atomicAdd(&offs[key], 1);
        g_sdesc[n * NBINS + rank] = desc;
    }
}

__global__ __launch_bounds__(352)
void pool_kernel(const float* __restrict__ f, float* __restrict__ out)
{
    const int n = blockIdx.x;   // proposal
    const int c = blockIdx.y;   // channel
    const int tid = threadIdx.x;
    const int t = min(tid, NBINS - 1);   // tail lanes shadow slot 342 (no store)

    __shared__ float res[NBINS];

    const int desc  = g_sdesc[n * NBINS + t];
    const int start =  desc        & 0x7FFF;
    const int bin   = (desc >> 15) & 0x1FF;
    const int nd    = (desc >> 24) & 3;
    const int nh    = (desc >> 26) & 3;
    const int nw    = (desc >> 28) & 3;

    const float* base = f + g_base[n] + (c << 15) + start;

    // warp-uniform exact trip counts (sorted by class)
    float m = -FLT_MAX;
    for (int d = 0; d <= nd; ++d)
        for (int h = 0; h <= nh; ++h) {
            const float* row = base + (d << 10) + (h << 5);
            for (int w = 0; w <= nw; ++w)
                m = fmaxf(m, __ldg(row + w));
        }

    if (tid < NBINS) res[bin] = m;       // smem transpose for coalesced STG
    __syncthreads();

    if (tid < NBINS)
        out[(size_t)(n * 64 + c) * NBINS + tid] = res[tid];
}

extern "C" void kernel_launch(void* const* d_in, const int* in_sizes, int n_in,
                              void* d_out, int out_size)
{
    const float* f     = (const float*)d_in[0];
    const float* props = (const float*)d_in[2];
    float* out = (float*)d_out;

    const int N = in_sizes[2] / 8;   // 96

    precompute_kernel<<<N, 352>>>(props);
    pool_kernel<<<dim3(N, 64), 352>>>(f, out);
}

// round 15
// speedup vs baseline: 1.1631x; 1.1631x over previous
#include <cuda_runtime.h>
#include <float.h>
#include <math.h>

// CropRoi: f (4,64,32,32,32) f32; proposals (96,8) f32; out (96,64,7,7,7) f32.
// Box: c0 = max(floor((c-s/2)/4),0), c1 = min(ceil((c+s/2)/4),32); L in [1,14].
// Adaptive windows per axis: size 1..3, always in-range -> plain max; clamped
// duplicate taps are harmless under max and add no wavefronts (same lines).
//
// Fusion of the two best measured ideas:
//  - R3: 8 channels per thread  -> MLP=8, desc/loop cost amortized 8x
//  - R12: warp-uniform clamped loops -> zero divergence replay; the clamp ALU
//    (its killer at CH=1) is now amortized over 8 LDGs per tap
//  - bin-order warps (NOT class-sorted) keep taps spatially clustered -> few
//    L1 wavefronts per warp-LDG (R14 lesson)
// Single kernel: each thread derives its own bin descriptor inline (~50 ALU,
// ~1us chip-wide at 768 blocks) -- cheaper than a precompute kernel + edge.

#define RBINS 7
#define NBINS 343
#define FDIM 32
#define CH 8

__global__ __launch_bounds__(352)
void crop_pool_kernel(const float* __restrict__ f,
                      const float* __restrict__ props,
                      float* __restrict__ out)
{
    const int n  = blockIdx.x;          // proposal
    const int cg = blockIdx.y * CH;     // first channel of this block
    const int tid = threadIdx.x;
    const int t = min(tid, NBINS - 1);  // tail lanes shadow bin 342 (no store)

    // ---- proposal row: [b, score, cx, cy, cz, sx, sy, sz] ----
    const float4 pa = __ldg((const float4*)(props + n * 8));
    const float4 pb = __ldg((const float4*)(props + n * 8) + 1);
    const int b = (int)pa.x;

    int c0d, Ld, c0h, Lh, c0w, Lw;
    {
        int lo = (int)floorf((pa.z - pb.y * 0.5f) * 0.25f);
        int hi = (int)ceilf ((pa.z + pb.y * 0.5f) * 0.25f);
        lo = max(lo, 0); hi = min(hi, FDIM); c0d = lo; Ld = max(hi - lo, 1);
    }
    {
        int lo = (int)floorf((pa.w - pb.z * 0.5f) * 0.25f);
        int hi = (int)ceilf ((pa.w + pb.z * 0.5f) * 0.25f);
        lo = max(lo, 0); hi = min(hi, FDIM); c0h = lo; Lh = max(hi - lo, 1);
    }
    {
        int lo = (int)floorf((pb.x - pb.w * 0.5f) * 0.25f);
        int hi = (int)ceilf ((pb.x + pb.w * 0.5f) * 0.25f);
        lo = max(lo, 0); hi = min(hi, FDIM); c0w = lo; Lw = max(hi - lo, 1);
    }

    // ---- this thread's bin -> window bounds (const div by 49/7 = mul/shift)
    const int i = t / 49;
    const int r = t - i * 49;
    const int j = r / RBINS;
    const int k = r - j * RBINS;

    const int ds = (i * Ld) / RBINS, de = ((i + 1) * Ld + RBINS - 1) / RBINS;
    const int hs = (j * Lh) / RBINS, he = ((j + 1) * Lh + RBINS - 1) / RBINS;
    const int ws = (k * Lw) / RBINS, we = ((k + 1) * Lw + RBINS - 1) / RBINS;

    const int nd = de - ds - 1, nh = he - hs - 1, nw = we - ws - 1;   // 0..2

    // warp-uniform trip counts (zero divergence replay)
    const int ndw = __reduce_max_sync(0xFFFFFFFFu, nd);
    const int nhw = __reduce_max_sync(0xFFFFFFFFu, nh);
    const int nww = __reduce_max_sync(0xFFFFFFFFu, nw);

    const float* base = f + (((size_t)(b * 64 + cg)) << 15)
                          + (((c0d + ds) * FDIM + (c0h + hs)) * FDIM + (c0w + ws));

    float m0 = -FLT_MAX, m1 = -FLT_MAX, m2 = -FLT_MAX, m3 = -FLT_MAX;
    float m4 = -FLT_MAX, m5 = -FLT_MAX, m6 = -FLT_MAX, m7 = -FLT_MAX;

    for (int d = 0; d <= ndw; ++d) {
        const int doff = min(d, nd) << 10;
        for (int h = 0; h <= nhw; ++h) {
            const int hoff = doff + (min(h, nh) << 5);
            for (int w = 0; w <= nww; ++w) {
                const float* e = base + hoff + min(w, nw);
                // 8 independent loads (128KB channel stride, immediate offsets)
                m0 = fmaxf(m0, __ldg(e + (0 << 15)));
                m1 = fmaxf(m1, __ldg(e + (1 << 15)));
                m2 = fmaxf(m2, __ldg(e + (2 << 15)));
                m3 = fmaxf(m3, __ldg(e + (3 << 15)));
                m4 = fmaxf(m4, __ldg(e + (4 << 15)));
                m5 = fmaxf(m5, __ldg(e + (5 << 15)));
                m6 = fmaxf(m6, __ldg(e + (6 << 15)));
                m7 = fmaxf(m7, __ldg(e + (7 << 15)));
            }
        }
    }

    if (tid < NBINS) {
        float* op = out + (size_t)(n * 64 + cg) * NBINS + tid;
        op[0 * NBINS] = m0;
        op[1 * NBINS] = m1;
        op[2 * NBINS] = m2;
        op[3 * NBINS] = m3;
        op[4 * NBINS] = m4;
        op[5 * NBINS] = m5;
        op[6 * NBINS] = m6;
        op[7 * NBINS] = m7;
    }
}

extern "C" void kernel_launch(void* const* d_in, const int* in_sizes, int n_in,
                              void* d_out, int out_size)
{
    const float* f     = (const float*)d_in[0];
    const float* props = (const float*)d_in[2];
    float* out = (float*)d_out;

    const int N = in_sizes[2] / 8;   // 96

    crop_pool_kernel<<<dim3(N, 64 / CH), 352>>>(f, props, out);
}